// round 1
// baseline (speedup 1.0000x reference)
#include <cuda_runtime.h>

#define BATCH 16
#define C 512
#define HW 1024
#define G 32
#define CG 16
#define EPS 1e-5f

// Scratch (device globals: allocation-free per harness rules)
__device__ float g_h[BATCH * C * HW];   // groupnorm output
__device__ float g_q[BATCH * C * HW];
__device__ float g_k[BATCH * C * HW];
__device__ float g_v[BATCH * C * HW];
__device__ float g_s[(size_t)BATCH * HW * HW];  // attention scores / probs
__device__ float g_o[BATCH * C * HW];   // attention output

// ---------------------------------------------------------------------------
// GroupNorm: one block per (batch, group). Reduce 16 ch x 1024 pix = 16384 vals
// ---------------------------------------------------------------------------
__global__ void gn_kernel(const float* __restrict__ x,
                          const float* __restrict__ gw,
                          const float* __restrict__ gb) {
    int bg = blockIdx.x;
    int bb = bg / G, g = bg % G;
    const float* xp = x + ((size_t)bb * C + (size_t)g * CG) * HW;
    float* hp = g_h + ((size_t)bb * C + (size_t)g * CG) * HW;
    const int n = CG * HW;  // 16384

    float s = 0.f, ss = 0.f;
    for (int i = threadIdx.x; i < n; i += blockDim.x) {
        float v = xp[i];
        s += v;
        ss += v * v;
    }
    __shared__ float sh0[256], sh1[256];
    sh0[threadIdx.x] = s;
    sh1[threadIdx.x] = ss;
    __syncthreads();
    for (int o = 128; o > 0; o >>= 1) {
        if (threadIdx.x < o) {
            sh0[threadIdx.x] += sh0[threadIdx.x + o];
            sh1[threadIdx.x] += sh1[threadIdx.x + o];
        }
        __syncthreads();
    }
    float mu = sh0[0] / n;
    float var = sh1[0] / n - mu * mu;
    float rinv = rsqrtf(var + EPS);

    for (int i = threadIdx.x; i < n; i += blockDim.x) {
        int c = g * CG + (i >> 10);  // i / HW
        hp[i] = (xp[i] - mu) * rinv * gw[c] + gb[c];
    }
}

// ---------------------------------------------------------------------------
// GEMM tiling constants: 64x64 tile, K-step 16, 256 threads, 4x4 per thread
// ---------------------------------------------------------------------------
#define BM 64
#define BN 64
#define BK 16

// Out[b][m][n] = sum_k W[m][k] * Hin[b][k][n] + bias[m] (+ resid[b][m][n])
__global__ void gemm_wh(const float* __restrict__ W,
                        const float* __restrict__ bias,
                        const float* __restrict__ Hin,
                        float* __restrict__ Out,
                        const float* __restrict__ resid) {
    int bb = blockIdx.z;
    const float* Hp = Hin + (size_t)bb * C * HW;
    float* Op = Out + (size_t)bb * C * HW;
    int m0 = blockIdx.y * BM, n0 = blockIdx.x * BN;

    __shared__ float As[BK][BM];  // W^T tile: As[k][m]
    __shared__ float Bs[BK][BN];  // H tile:  Bs[k][n]

    int t = threadIdx.x;
    int tm = (t >> 4) * 4, tn = (t & 15) * 4;
    float acc[4][4] = {};

    for (int k0 = 0; k0 < C; k0 += BK) {
        {   // load + transpose W tile
            int mm = t >> 2, kk = (t & 3) * 4;
            float4 w4 = *(const float4*)&W[(size_t)(m0 + mm) * C + k0 + kk];
            As[kk + 0][mm] = w4.x; As[kk + 1][mm] = w4.y;
            As[kk + 2][mm] = w4.z; As[kk + 3][mm] = w4.w;
        }
        {   // load H tile
            int kk = t >> 4, nn = (t & 15) * 4;
            *(float4*)&Bs[kk][nn] =
                *(const float4*)&Hp[(size_t)(k0 + kk) * HW + n0 + nn];
        }
        __syncthreads();
#pragma unroll
        for (int kk = 0; kk < BK; kk++) {
            float4 a4 = *(float4*)&As[kk][tm];
            float4 b4 = *(float4*)&Bs[kk][tn];
            float a[4] = {a4.x, a4.y, a4.z, a4.w};
            float bv[4] = {b4.x, b4.y, b4.z, b4.w};
#pragma unroll
            for (int i = 0; i < 4; i++)
#pragma unroll
                for (int j = 0; j < 4; j++) acc[i][j] += a[i] * bv[j];
        }
        __syncthreads();
    }
#pragma unroll
    for (int i = 0; i < 4; i++) {
        float bval = bias[m0 + tm + i];
        size_t ro = (size_t)(m0 + tm + i) * HW + n0 + tn;
        if (resid) {
            const float* rp = resid + (size_t)bb * C * HW;
#pragma unroll
            for (int j = 0; j < 4; j++)
                Op[ro + j] = acc[i][j] + bval + rp[ro + j];
        } else {
#pragma unroll
            for (int j = 0; j < 4; j++) Op[ro + j] = acc[i][j] + bval;
        }
    }
}

// S[b][i][j] = scale * sum_c Q[b][c][i] * K[b][c][j]
__global__ void gemm_qk(const float* __restrict__ Q,
                        const float* __restrict__ K,
                        float* __restrict__ S, float scale) {
    int bb = blockIdx.z;
    const float* Qp = Q + (size_t)bb * C * HW;
    const float* Kp = K + (size_t)bb * C * HW;
    float* Sp = S + (size_t)bb * HW * HW;
    int i0 = blockIdx.y * BM, j0 = blockIdx.x * BN;

    __shared__ float As[BK][BM];  // Q[c][i]
    __shared__ float Bs[BK][BN];  // K[c][j]

    int t = threadIdx.x;
    int ti = (t >> 4) * 4, tj = (t & 15) * 4;
    float acc[4][4] = {};

    for (int c0 = 0; c0 < C; c0 += BK) {
        int kk = t >> 4, xx = (t & 15) * 4;
        *(float4*)&As[kk][xx] = *(const float4*)&Qp[(size_t)(c0 + kk) * HW + i0 + xx];
        *(float4*)&Bs[kk][xx] = *(const float4*)&Kp[(size_t)(c0 + kk) * HW + j0 + xx];
        __syncthreads();
#pragma unroll
        for (int kk2 = 0; kk2 < BK; kk2++) {
            float4 a4 = *(float4*)&As[kk2][ti];
            float4 b4 = *(float4*)&Bs[kk2][tj];
            float a[4] = {a4.x, a4.y, a4.z, a4.w};
            float bv[4] = {b4.x, b4.y, b4.z, b4.w};
#pragma unroll
            for (int i = 0; i < 4; i++)
#pragma unroll
                for (int j = 0; j < 4; j++) acc[i][j] += a[i] * bv[j];
        }
        __syncthreads();
    }
#pragma unroll
    for (int i = 0; i < 4; i++) {
        size_t ro = (size_t)(i0 + ti + i) * HW + j0 + tj;
#pragma unroll
        for (int j = 0; j < 4; j++) Sp[ro + j] = acc[i][j] * scale;
    }
}

// Row softmax over 1024 columns. One block (256 thr) per row, 4 elems/thread.
__global__ void softmax_kernel(float* __restrict__ S) {
    float* row = S + (size_t)blockIdx.x * HW;
    int t = threadIdx.x;
    float4 v = ((float4*)row)[t];

    __shared__ float sh[256];
    float m = fmaxf(fmaxf(v.x, v.y), fmaxf(v.z, v.w));
    sh[t] = m;
    __syncthreads();
    for (int o = 128; o > 0; o >>= 1) {
        if (t < o) sh[t] = fmaxf(sh[t], sh[t + o]);
        __syncthreads();
    }
    m = sh[0];
    __syncthreads();

    v.x = __expf(v.x - m); v.y = __expf(v.y - m);
    v.z = __expf(v.z - m); v.w = __expf(v.w - m);
    sh[t] = v.x + v.y + v.z + v.w;
    __syncthreads();
    for (int o = 128; o > 0; o >>= 1) {
        if (t < o) sh[t] += sh[t + o];
        __syncthreads();
    }
    float inv = 1.0f / sh[0];
    v.x *= inv; v.y *= inv; v.z *= inv; v.w *= inv;
    ((float4*)row)[t] = v;
}

// O[b][c][i] = sum_j V[b][c][j] * A[b][i][j]   (K dim = 1024, both K-major)
__global__ void gemm_av(const float* __restrict__ A,
                        const float* __restrict__ V,
                        float* __restrict__ O) {
    int bb = blockIdx.z;
    const float* Ap = A + (size_t)bb * HW * HW;
    const float* Vp = V + (size_t)bb * C * HW;
    float* Op = O + (size_t)bb * C * HW;
    int c0 = blockIdx.y * BM, i0 = blockIdx.x * BN;

    __shared__ float Vs[BK][BM];   // Vs[j][c]
    __shared__ float As_[BK][BN];  // As[j][i]

    int t = threadIdx.x;
    int tc = (t >> 4) * 4, ti = (t & 15) * 4;
    float acc[4][4] = {};

    for (int j0 = 0; j0 < HW; j0 += BK) {
        int mm = t >> 2, kk = (t & 3) * 4;
        float4 v4 = *(const float4*)&Vp[(size_t)(c0 + mm) * HW + j0 + kk];
        Vs[kk + 0][mm] = v4.x; Vs[kk + 1][mm] = v4.y;
        Vs[kk + 2][mm] = v4.z; Vs[kk + 3][mm] = v4.w;
        float4 a4 = *(const float4*)&Ap[(size_t)(i0 + mm) * HW + j0 + kk];
        As_[kk + 0][mm] = a4.x; As_[kk + 1][mm] = a4.y;
        As_[kk + 2][mm] = a4.z; As_[kk + 3][mm] = a4.w;
        __syncthreads();
#pragma unroll
        for (int kk2 = 0; kk2 < BK; kk2++) {
            float4 a4v = *(float4*)&Vs[kk2][tc];
            float4 b4v = *(float4*)&As_[kk2][ti];
            float a[4] = {a4v.x, a4v.y, a4v.z, a4v.w};
            float bv[4] = {b4v.x, b4v.y, b4v.z, b4v.w};
#pragma unroll
            for (int i = 0; i < 4; i++)
#pragma unroll
                for (int j = 0; j < 4; j++) acc[i][j] += a[i] * bv[j];
        }
        __syncthreads();
    }
#pragma unroll
    for (int i = 0; i < 4; i++) {
        size_t ro = (size_t)(c0 + tc + i) * HW + i0 + ti;
#pragma unroll
        for (int j = 0; j < 4; j++) Op[ro + j] = acc[i][j];
    }
}

// ---------------------------------------------------------------------------
extern "C" void kernel_launch(void* const* d_in, const int* in_sizes, int n_in,
                              void* d_out, int out_size) {
    const float* x    = (const float*)d_in[0];
    // d_in[1] = temb (unused by reference)
    const float* gn_w = (const float*)d_in[2];
    const float* gn_b = (const float*)d_in[3];
    const float* q_w  = (const float*)d_in[4];
    const float* q_b  = (const float*)d_in[5];
    const float* k_w  = (const float*)d_in[6];
    const float* k_b  = (const float*)d_in[7];
    const float* v_w  = (const float*)d_in[8];
    const float* v_b  = (const float*)d_in[9];
    const float* p_w  = (const float*)d_in[10];
    const float* p_b  = (const float*)d_in[11];
    float* out = (float*)d_out;

    float *hbuf, *qbuf, *kbuf, *vbuf, *sbuf, *obuf;
    cudaGetSymbolAddress((void**)&hbuf, g_h);
    cudaGetSymbolAddress((void**)&qbuf, g_q);
    cudaGetSymbolAddress((void**)&kbuf, g_k);
    cudaGetSymbolAddress((void**)&vbuf, g_v);
    cudaGetSymbolAddress((void**)&sbuf, g_s);
    cudaGetSymbolAddress((void**)&obuf, g_o);

    // 1) GroupNorm
    gn_kernel<<<BATCH * G, 256>>>(x, gn_w, gn_b);

    // 2) Q, K, V projections
    dim3 gproj(HW / BN, C / BM, BATCH);
    gemm_wh<<<gproj, 256>>>(q_w, q_b, hbuf, qbuf, nullptr);
    gemm_wh<<<gproj, 256>>>(k_w, k_b, hbuf, kbuf, nullptr);
    gemm_wh<<<gproj, 256>>>(v_w, v_b, hbuf, vbuf, nullptr);

    // 3) scores = Q^T K * C^-0.5
    dim3 gqk(HW / BN, HW / BM, BATCH);
    const float scale = 0.044194173824159216f;  // 512^-0.5
    gemm_qk<<<gqk, 256>>>(qbuf, kbuf, sbuf, scale);

    // 4) softmax rows
    softmax_kernel<<<BATCH * HW, 256>>>(sbuf);

    // 5) O = attn @ V
    dim3 gav(HW / BN, C / BM, BATCH);
    gemm_av<<<gav, 256>>>(sbuf, vbuf, obuf);

    // 6) out = x + proj(O)
    gemm_wh<<<gproj, 256>>>(p_w, p_b, obuf, out, x);
}

// round 2
// speedup vs baseline: 1.1670x; 1.1670x over previous
#include <cuda_runtime.h>

#define BATCH 16
#define C 512
#define HW 1024
#define G 32
#define CG 16
#define EPS 1e-5f

// Scratch (device globals: allocation-free per harness rules)
__device__ float g_h[BATCH * C * HW];
__device__ float g_q[BATCH * C * HW];
__device__ float g_k[BATCH * C * HW];
__device__ float g_v[BATCH * C * HW];
__device__ float g_s[(size_t)BATCH * HW * HW];
__device__ float g_o[BATCH * C * HW];

// ---------------------------------------------------------------------------
// GroupNorm: one block per (batch, group)
// ---------------------------------------------------------------------------
__global__ void gn_kernel(const float* __restrict__ x,
                          const float* __restrict__ gw,
                          const float* __restrict__ gb) {
    int bg = blockIdx.x;
    int bb = bg / G, g = bg % G;
    const float* xp = x + ((size_t)bb * C + (size_t)g * CG) * HW;
    float* hp = g_h + ((size_t)bb * C + (size_t)g * CG) * HW;
    const int n = CG * HW;

    float s = 0.f, ss = 0.f;
    for (int i = threadIdx.x; i < n; i += blockDim.x) {
        float v = xp[i];
        s += v;
        ss += v * v;
    }
    __shared__ float sh0[256], sh1[256];
    sh0[threadIdx.x] = s;
    sh1[threadIdx.x] = ss;
    __syncthreads();
    for (int o = 128; o > 0; o >>= 1) {
        if (threadIdx.x < o) {
            sh0[threadIdx.x] += sh0[threadIdx.x + o];
            sh1[threadIdx.x] += sh1[threadIdx.x + o];
        }
        __syncthreads();
    }
    float mu = sh0[0] / n;
    float var = sh1[0] / n - mu * mu;
    float rinv = rsqrtf(var + EPS);

    for (int i = threadIdx.x; i < n; i += blockDim.x) {
        int c = g * CG + (i >> 10);
        hp[i] = (xp[i] - mu) * rinv * gw[c] + gb[c];
    }
}

// ---------------------------------------------------------------------------
// GEMM: 128x128 tile, BK=8, 256 threads, 8x8 microtile
// ---------------------------------------------------------------------------
#define TBM 128
#define TBN 128
#define TBK 8

// inner product step shared by all GEMMs
__device__ __forceinline__ void mt_step(const float (*As)[TBM],
                                        const float (*Bs)[TBN],
                                        int ty4, int tx4, float acc[8][8]) {
#pragma unroll
    for (int kk = 0; kk < TBK; kk++) {
        float4 a0 = *(const float4*)&As[kk][ty4];
        float4 a1 = *(const float4*)&As[kk][ty4 + 64];
        float4 b0 = *(const float4*)&Bs[kk][tx4];
        float4 b1 = *(const float4*)&Bs[kk][tx4 + 64];
        float a[8] = {a0.x, a0.y, a0.z, a0.w, a1.x, a1.y, a1.z, a1.w};
        float b[8] = {b0.x, b0.y, b0.z, b0.w, b1.x, b1.y, b1.z, b1.w};
#pragma unroll
        for (int i = 0; i < 8; i++)
#pragma unroll
            for (int j = 0; j < 8; j++) acc[i][j] += a[i] * b[j];
    }
}

// Out[b][m][n] = sum_k W[m][k]*H[b][k][n] + bias[m] (+resid)
__global__ void __launch_bounds__(256, 2)
gemm_wh(const float* __restrict__ W, const float* __restrict__ bias,
        const float* __restrict__ Hin, float* __restrict__ Out,
        const float* __restrict__ resid) {
    int bb = blockIdx.z;
    const float* Hp = Hin + (size_t)bb * C * HW;
    float* Op = Out + (size_t)bb * C * HW;
    int m0 = blockIdx.y * TBM, n0 = blockIdx.x * TBN;

    __shared__ float As[TBK][TBM];
    __shared__ float Bs[TBK][TBN];

    int t = threadIdx.x;
    int tx4 = (t & 15) * 4, ty4 = (t >> 4) * 4;
    int arow = t >> 1, acol = (t & 1) * 4;   // W (transpose-load)
    int brow = t >> 5, bcol = (t & 31) * 4;  // H (direct)
    float acc[8][8] = {};

    for (int k0 = 0; k0 < C; k0 += TBK) {
        float4 w4 = *(const float4*)&W[(size_t)(m0 + arow) * C + k0 + acol];
        As[acol + 0][arow] = w4.x; As[acol + 1][arow] = w4.y;
        As[acol + 2][arow] = w4.z; As[acol + 3][arow] = w4.w;
        *(float4*)&Bs[brow][bcol] =
            *(const float4*)&Hp[(size_t)(k0 + brow) * HW + n0 + bcol];
        __syncthreads();
        mt_step(As, Bs, ty4, tx4, acc);
        __syncthreads();
    }
#pragma unroll
    for (int i = 0; i < 8; i++) {
        int m = m0 + ty4 + (i < 4 ? i : 60 + i);
        float bv = bias[m];
        size_t ro = (size_t)m * HW + n0;
        if (resid) {
            const float* rp = resid + (size_t)bb * C * HW;
#pragma unroll
            for (int j = 0; j < 8; j++) {
                int n = tx4 + (j < 4 ? j : 60 + j);
                Op[ro + n] = acc[i][j] + bv + rp[ro + n];
            }
        } else {
#pragma unroll
            for (int j = 0; j < 8; j++) {
                int n = tx4 + (j < 4 ? j : 60 + j);
                Op[ro + n] = acc[i][j] + bv;
            }
        }
    }
}

// S[b][i][j] = scale * sum_c Q[b][c][i]*K[b][c][j]
__global__ void __launch_bounds__(256, 2)
gemm_qk(const float* __restrict__ Q, const float* __restrict__ K,
        float* __restrict__ S, float scale) {
    int bb = blockIdx.z;
    const float* Qp = Q + (size_t)bb * C * HW;
    const float* Kp = K + (size_t)bb * C * HW;
    float* Sp = S + (size_t)bb * HW * HW;
    int i0 = blockIdx.y * TBM, j0 = blockIdx.x * TBN;

    __shared__ float As[TBK][TBM];
    __shared__ float Bs[TBK][TBN];

    int t = threadIdx.x;
    int tx4 = (t & 15) * 4, ty4 = (t >> 4) * 4;
    int kr = t >> 5, xc = (t & 31) * 4;  // both direct loads
    float acc[8][8] = {};

    for (int c0 = 0; c0 < C; c0 += TBK) {
        *(float4*)&As[kr][xc] =
            *(const float4*)&Qp[(size_t)(c0 + kr) * HW + i0 + xc];
        *(float4*)&Bs[kr][xc] =
            *(const float4*)&Kp[(size_t)(c0 + kr) * HW + j0 + xc];
        __syncthreads();
        mt_step(As, Bs, ty4, tx4, acc);
        __syncthreads();
    }
#pragma unroll
    for (int i = 0; i < 8; i++) {
        int m = i0 + ty4 + (i < 4 ? i : 60 + i);
        size_t ro = (size_t)m * HW + j0;
#pragma unroll
        for (int j = 0; j < 8; j++) {
            int n = tx4 + (j < 4 ? j : 60 + j);
            Sp[ro + n] = acc[i][j] * scale;
        }
    }
}

// O[b][c][i] = sum_j V[b][c][j] * A[b][i][j]  (both K-contiguous)
__global__ void __launch_bounds__(256, 2)
gemm_av(const float* __restrict__ A, const float* __restrict__ V,
        float* __restrict__ O) {
    int bb = blockIdx.z;
    const float* Ap = A + (size_t)bb * HW * HW;
    const float* Vp = V + (size_t)bb * C * HW;
    float* Op = O + (size_t)bb * C * HW;
    int c0 = blockIdx.y * TBM, i0 = blockIdx.x * TBN;

    __shared__ float Vs[TBK][TBM];
    __shared__ float As_[TBK][TBN];

    int t = threadIdx.x;
    int tx4 = (t & 15) * 4, ty4 = (t >> 4) * 4;
    int arow = t >> 1, acol = (t & 1) * 4;  // both transpose-loads
    float acc[8][8] = {};

    for (int j0 = 0; j0 < HW; j0 += TBK) {
        float4 v4 = *(const float4*)&Vp[(size_t)(c0 + arow) * HW + j0 + acol];
        Vs[acol + 0][arow] = v4.x; Vs[acol + 1][arow] = v4.y;
        Vs[acol + 2][arow] = v4.z; Vs[acol + 3][arow] = v4.w;
        float4 a4 = *(const float4*)&Ap[(size_t)(i0 + arow) * HW + j0 + acol];
        As_[acol + 0][arow] = a4.x; As_[acol + 1][arow] = a4.y;
        As_[acol + 2][arow] = a4.z; As_[acol + 3][arow] = a4.w;
        __syncthreads();
        mt_step(Vs, As_, ty4, tx4, acc);
        __syncthreads();
    }
#pragma unroll
    for (int i = 0; i < 8; i++) {
        int m = c0 + ty4 + (i < 4 ? i : 60 + i);
        size_t ro = (size_t)m * HW + i0;
#pragma unroll
        for (int j = 0; j < 8; j++) {
            int n = tx4 + (j < 4 ? j : 60 + j);
            Op[ro + n] = acc[i][j];
        }
    }
}

// Row softmax over 1024 columns
__global__ void softmax_kernel(float* __restrict__ S) {
    float* row = S + (size_t)blockIdx.x * HW;
    int t = threadIdx.x;
    float4 v = ((float4*)row)[t];

    __shared__ float sh[256];
    float m = fmaxf(fmaxf(v.x, v.y), fmaxf(v.z, v.w));
    sh[t] = m;
    __syncthreads();
    for (int o = 128; o > 0; o >>= 1) {
        if (t < o) sh[t] = fmaxf(sh[t], sh[t + o]);
        __syncthreads();
    }
    m = sh[0];
    __syncthreads();

    v.x = __expf(v.x - m); v.y = __expf(v.y - m);
    v.z = __expf(v.z - m); v.w = __expf(v.w - m);
    sh[t] = v.x + v.y + v.z + v.w;
    __syncthreads();
    for (int o = 128; o > 0; o >>= 1) {
        if (t < o) sh[t] += sh[t + o];
        __syncthreads();
    }
    float inv = 1.0f / sh[0];
    v.x *= inv; v.y *= inv; v.z *= inv; v.w *= inv;
    ((float4*)row)[t] = v;
}

// ---------------------------------------------------------------------------
extern "C" void kernel_launch(void* const* d_in, const int* in_sizes, int n_in,
                              void* d_out, int out_size) {
    const float* x    = (const float*)d_in[0];
    const float* gn_w = (const float*)d_in[2];
    const float* gn_b = (const float*)d_in[3];
    const float* q_w  = (const float*)d_in[4];
    const float* q_b  = (const float*)d_in[5];
    const float* k_w  = (const float*)d_in[6];
    const float* k_b  = (const float*)d_in[7];
    const float* v_w  = (const float*)d_in[8];
    const float* v_b  = (const float*)d_in[9];
    const float* p_w  = (const float*)d_in[10];
    const float* p_b  = (const float*)d_in[11];
    float* out = (float*)d_out;

    float *hbuf, *qbuf, *kbuf, *vbuf, *sbuf, *obuf;
    cudaGetSymbolAddress((void**)&hbuf, g_h);
    cudaGetSymbolAddress((void**)&qbuf, g_q);
    cudaGetSymbolAddress((void**)&kbuf, g_k);
    cudaGetSymbolAddress((void**)&vbuf, g_v);
    cudaGetSymbolAddress((void**)&sbuf, g_s);
    cudaGetSymbolAddress((void**)&obuf, g_o);

    gn_kernel<<<BATCH * G, 256>>>(x, gn_w, gn_b);

    dim3 gproj(HW / TBN, C / TBM, BATCH);         // (8,4,16)
    gemm_wh<<<gproj, 256>>>(q_w, q_b, hbuf, qbuf, nullptr);
    gemm_wh<<<gproj, 256>>>(k_w, k_b, hbuf, kbuf, nullptr);
    gemm_wh<<<gproj, 256>>>(v_w, v_b, hbuf, vbuf, nullptr);

    dim3 gqk(HW / TBN, HW / TBM, BATCH);          // (8,8,16)
    const float scale = 0.044194173824159216f;    // 512^-0.5
    gemm_qk<<<gqk, 256>>>(qbuf, kbuf, sbuf, scale);

    softmax_kernel<<<BATCH * HW, 256>>>(sbuf);

    dim3 gav(HW / TBN, C / TBM, BATCH);           // (8,4,16)
    gemm_av<<<gav, 256>>>(sbuf, vbuf, obuf);

    gemm_wh<<<gproj, 256>>>(p_w, p_b, obuf, out, x);
}

// round 4
// speedup vs baseline: 2.2686x; 1.9440x over previous
#include <cuda_runtime.h>
#include <cuda_bf16.h>
#include <cstdint>

#define BATCH 16
#define CC 512
#define HW 1024
#define G 32
#define CG 16
#define EPS 1e-5f

typedef __nv_bfloat16 bf16;

// ---------------------------------------------------------------------------
// Scratch (device globals)
// ---------------------------------------------------------------------------
__device__ float g_stats[BATCH * G * 2];
__device__ __align__(16) bf16 g_ht_hi[BATCH * HW * CC], g_ht_lo[BATCH * HW * CC];
__device__ __align__(16) bf16 g_qt_hi[BATCH * HW * CC], g_qt_lo[BATCH * HW * CC];
__device__ __align__(16) bf16 g_kt_hi[BATCH * HW * CC], g_kt_lo[BATCH * HW * CC];
__device__ __align__(16) bf16 g_v_hi[BATCH * CC * HW],  g_v_lo[BATCH * CC * HW];
__device__ __align__(16) float g_s[(size_t)BATCH * HW * HW];
__device__ __align__(16) bf16 g_p_hi[(size_t)BATCH * HW * HW];
__device__ __align__(16) bf16 g_p_lo[(size_t)BATCH * HW * HW];
__device__ __align__(16) bf16 g_ot_hi[BATCH * HW * CC], g_ot_lo[BATCH * HW * CC];
__device__ __align__(16) bf16 g_w_hi[4 * CC * CC], g_w_lo[4 * CC * CC];

// ---------------------------------------------------------------------------
// PTX helpers (plain sm_80+ features only: cp.async + mma.sync)
// ---------------------------------------------------------------------------
__device__ __forceinline__ uint32_t smem_u32(const void* p) {
    uint32_t a;
    asm("{ .reg .u64 t; cvta.to.shared.u64 t, %1; cvt.u32.u64 %0, t; }"
        : "=r"(a) : "l"(p));
    return a;
}
__device__ __forceinline__ void cpa16(uint32_t dst, const void* src) {
    asm volatile("cp.async.ca.shared.global [%0], [%1], 16;"
                 :: "r"(dst), "l"(src));
}
#define CP_COMMIT() asm volatile("cp.async.commit_group;" ::: "memory")
#define CP_WAIT1() asm volatile("cp.async.wait_group 1;" ::: "memory")
#define CP_WAIT0() asm volatile("cp.async.wait_group 0;" ::: "memory")

__device__ __forceinline__ uint32_t lds32(uint32_t a) {
    uint32_t v;
    asm volatile("ld.shared.b32 %0, [%1];" : "=r"(v) : "r"(a));
    return v;
}
__device__ __forceinline__ void mma16816(float* c, const uint32_t* a,
                                         const uint32_t* b) {
    asm volatile(
        "mma.sync.aligned.m16n8k16.row.col.f32.bf16.bf16.f32 "
        "{%0,%1,%2,%3}, {%4,%5,%6,%7}, {%8,%9}, {%0,%1,%2,%3};"
        : "+f"(c[0]), "+f"(c[1]), "+f"(c[2]), "+f"(c[3])
        : "r"(a[0]), "r"(a[1]), "r"(a[2]), "r"(a[3]), "r"(b[0]), "r"(b[1]));
}

// ---------------------------------------------------------------------------
// Split-bf16 MMA GEMM: D[m][n] = sum_k A[m][k]*B[n][k]  (both K-contiguous)
// 128x128 block tile, BK=32, 256 thr (8 warps, 32x64 warp tiles), cp.async x2.
// MODE 0: +bias[n], bf16 hi/lo out     (Q/K proj)
// MODE 1: +bias[m], bf16 hi/lo out     (V proj)
// MODE 2: *scale,   f32 out            (scores)
// MODE 3: plain,    bf16 hi/lo out     (attn @ V)
// MODE 4: +bias[m]+resid, f32 out      (final proj)
// ---------------------------------------------------------------------------
#define PADB 80u             // bytes per smem row (40 bf16, conflict-free)
#define MATB 10240u          // 128 rows * 80 B
#define STAGEB 40960u        // 4 matrices
#define SMEM_TOTAL (2 * STAGEB)

template <int MODE>
__global__ void __launch_bounds__(256)
gemm_mma(const bf16* __restrict__ Ahi, const bf16* __restrict__ Alo, size_t sA,
         const bf16* __restrict__ Bhi, const bf16* __restrict__ Blo, size_t sB,
         int K, const float* __restrict__ bias, float scale,
         const float* __restrict__ resid,
         bf16* __restrict__ Ohi, bf16* __restrict__ Olo, float* __restrict__ Of,
         int ldO, size_t sO) {
    extern __shared__ char smem[];
    const uint32_t sb = smem_u32(smem);

    const int t = threadIdx.x;
    const int w = t >> 5, lane = t & 31;
    const int g = lane >> 2, tg = lane & 3;
    const int wm = (w >> 1) * 32, wn = (w & 1) * 64;
    const int bz = blockIdx.z;
    const int n0 = blockIdx.x * 128, m0 = blockIdx.y * 128;

    const bf16* arh = Ahi + bz * sA + (size_t)m0 * K;
    const bf16* arl = Alo + bz * sA + (size_t)m0 * K;
    const bf16* brh = Bhi + bz * sB + (size_t)n0 * K;
    const bf16* brl = Blo + bz * sB + (size_t)n0 * K;

    float acc[2][8][4];
#pragma unroll
    for (int i = 0; i < 2; i++)
#pragma unroll
        for (int j = 0; j < 8; j++)
#pragma unroll
            for (int e = 0; e < 4; e++) acc[i][j][e] = 0.f;

    const int row_l = t >> 2, c16 = t & 3;       // loader mapping (id = t, t+256)
    const uint32_t soff0 = (uint32_t)row_l * PADB + c16 * 16;
    const int row_l2 = (t + 256) >> 2, c16b = t & 3;  // (t+256)&3 == t&3
    const uint32_t soff1 = (uint32_t)row_l2 * PADB + c16b * 16;

    const int nsteps = K >> 5;

    // prologue: stage 0
    {
        size_t g0 = (size_t)row_l * K + c16 * 8;
        size_t g1 = (size_t)row_l2 * K + c16b * 8;
        uint32_t b0 = sb;
        cpa16(b0 + soff0, arh + g0);            cpa16(b0 + soff1, arh + g1);
        cpa16(b0 + MATB + soff0, arl + g0);     cpa16(b0 + MATB + soff1, arl + g1);
        cpa16(b0 + 2 * MATB + soff0, brh + g0); cpa16(b0 + 2 * MATB + soff1, brh + g1);
        cpa16(b0 + 3 * MATB + soff0, brl + g0); cpa16(b0 + 3 * MATB + soff1, brl + g1);
        CP_COMMIT();
    }

    for (int s = 0; s < nsteps; s++) {
        if (s + 1 < nsteps) {
            int k0 = (s + 1) << 5;
            uint32_t b0 = sb + ((s + 1) & 1) * STAGEB;
            size_t g0 = (size_t)row_l * K + k0 + c16 * 8;
            size_t g1 = (size_t)row_l2 * K + k0 + c16b * 8;
            cpa16(b0 + soff0, arh + g0);            cpa16(b0 + soff1, arh + g1);
            cpa16(b0 + MATB + soff0, arl + g0);     cpa16(b0 + MATB + soff1, arl + g1);
            cpa16(b0 + 2 * MATB + soff0, brh + g0); cpa16(b0 + 2 * MATB + soff1, brh + g1);
            cpa16(b0 + 3 * MATB + soff0, brl + g0); cpa16(b0 + 3 * MATB + soff1, brl + g1);
            CP_COMMIT();
            CP_WAIT1();
        } else {
            CP_WAIT0();
        }
        __syncthreads();

        uint32_t stg = sb + (s & 1) * STAGEB;
        uint32_t pAh = stg, pAl = stg + MATB, pBh = stg + 2 * MATB,
                 pBl = stg + 3 * MATB;
#pragma unroll
        for (int kk = 0; kk < 2; kk++) {
            uint32_t kb = kk * 32 + tg * 4;  // k16 byte offset within row
            uint32_t Ah[2][4], Al[2][4];
#pragma unroll
            for (int mf = 0; mf < 2; mf++) {
                uint32_t r0 = (uint32_t)(wm + mf * 16 + g) * PADB + kb;
                Ah[mf][0] = lds32(pAh + r0);
                Ah[mf][1] = lds32(pAh + r0 + 8 * PADB);
                Ah[mf][2] = lds32(pAh + r0 + 16);
                Ah[mf][3] = lds32(pAh + r0 + 8 * PADB + 16);
                Al[mf][0] = lds32(pAl + r0);
                Al[mf][1] = lds32(pAl + r0 + 8 * PADB);
                Al[mf][2] = lds32(pAl + r0 + 16);
                Al[mf][3] = lds32(pAl + r0 + 8 * PADB + 16);
            }
#pragma unroll
            for (int nf = 0; nf < 8; nf++) {
                uint32_t rn = (uint32_t)(wn + nf * 8 + g) * PADB + kb;
                uint32_t Bh[2], Bl[2];
                Bh[0] = lds32(pBh + rn);
                Bh[1] = lds32(pBh + rn + 16);
                Bl[0] = lds32(pBl + rn);
                Bl[1] = lds32(pBl + rn + 16);
#pragma unroll
                for (int mf = 0; mf < 2; mf++) {
                    mma16816(acc[mf][nf], Ah[mf], Bh);
                    mma16816(acc[mf][nf], Ah[mf], Bl);
                    mma16816(acc[mf][nf], Al[mf], Bh);
                }
            }
        }
        __syncthreads();
    }

    // ---- epilogue: direct row-major [m][n] store -------------------------
#pragma unroll
    for (int mf = 0; mf < 2; mf++) {
        int mA = m0 + wm + mf * 16 + g;
        int mB = mA + 8;
        float bmA = 0.f, bmB = 0.f;
        if (MODE == 1 || MODE == 4) { bmA = bias[mA]; bmB = bias[mB]; }
#pragma unroll
        for (int nf = 0; nf < 8; nf++) {
            int n = n0 + wn + nf * 8 + tg * 2;
            float v0 = acc[mf][nf][0], v1 = acc[mf][nf][1];
            float v2 = acc[mf][nf][2], v3 = acc[mf][nf][3];
            if (MODE == 0) {
                float bn0 = bias[n], bn1 = bias[n + 1];
                v0 += bn0; v1 += bn1; v2 += bn0; v3 += bn1;
            }
            if (MODE == 1 || MODE == 4) { v0 += bmA; v1 += bmA; v2 += bmB; v3 += bmB; }
            if (MODE == 2) { v0 *= scale; v1 *= scale; v2 *= scale; v3 *= scale; }
            size_t iA = bz * sO + (size_t)mA * ldO + n;
            size_t iB = bz * sO + (size_t)mB * ldO + n;
            if (MODE == 4) {
                v0 += resid[iA]; v1 += resid[iA + 1];
                v2 += resid[iB]; v3 += resid[iB + 1];
            }
            if (MODE == 2 || MODE == 4) {
                *(float2*)&Of[iA] = make_float2(v0, v1);
                *(float2*)&Of[iB] = make_float2(v2, v3);
            } else {
                bf16 h0 = __float2bfloat16(v0), h1 = __float2bfloat16(v1);
                bf16 h2 = __float2bfloat16(v2), h3 = __float2bfloat16(v3);
                __nv_bfloat162 hA; hA.x = h0; hA.y = h1;
                __nv_bfloat162 hB; hB.x = h2; hB.y = h3;
                *(__nv_bfloat162*)&Ohi[iA] = hA;
                *(__nv_bfloat162*)&Ohi[iB] = hB;
                __nv_bfloat162 lA, lB;
                lA.x = __float2bfloat16(v0 - __bfloat162float(h0));
                lA.y = __float2bfloat16(v1 - __bfloat162float(h1));
                lB.x = __float2bfloat16(v2 - __bfloat162float(h2));
                lB.y = __float2bfloat16(v3 - __bfloat162float(h3));
                *(__nv_bfloat162*)&Olo[iA] = lA;
                *(__nv_bfloat162*)&Olo[iB] = lB;
            }
        }
    }
}

// ---------------------------------------------------------------------------
// GroupNorm stats
// ---------------------------------------------------------------------------
__global__ void gn_stats(const float* __restrict__ x) {
    int bg = blockIdx.x;
    int bb = bg / G, g = bg % G;
    const float* xp = x + ((size_t)bb * CC + (size_t)g * CG) * HW;
    const int n = CG * HW;

    float s = 0.f, ss = 0.f;
    for (int i = threadIdx.x; i < n; i += blockDim.x) {
        float v = xp[i];
        s += v;
        ss += v * v;
    }
    __shared__ float sh0[256], sh1[256];
    sh0[threadIdx.x] = s;
    sh1[threadIdx.x] = ss;
    __syncthreads();
    for (int o = 128; o > 0; o >>= 1) {
        if (threadIdx.x < o) {
            sh0[threadIdx.x] += sh0[threadIdx.x + o];
            sh1[threadIdx.x] += sh1[threadIdx.x + o];
        }
        __syncthreads();
    }
    if (threadIdx.x == 0) {
        float mu = sh0[0] / n;
        float var = sh1[0] / n - mu * mu;
        g_stats[bg * 2] = mu;
        g_stats[bg * 2 + 1] = rsqrtf(var + EPS);
    }
}

// GroupNorm apply + transpose: x[b][c][i] -> Ht[b][i][c] bf16 hi/lo
__global__ void gn_transpose(const float* __restrict__ x,
                             const float* __restrict__ gw,
                             const float* __restrict__ gb) {
    __shared__ float tile[32][33];
    int bz = blockIdx.z;
    int i0 = blockIdx.x * 32, c0 = blockIdx.y * 32;
    int tx = threadIdx.x, ty = threadIdx.y;
    const float* xb = x + (size_t)bz * CC * HW;
#pragma unroll
    for (int r = 0; r < 4; r++) {
        int c = c0 + ty + r * 8;
        float mu = g_stats[(bz * G + (c >> 4)) * 2];
        float ri = g_stats[(bz * G + (c >> 4)) * 2 + 1];
        float v = xb[(size_t)c * HW + i0 + tx];
        tile[ty + r * 8][tx] = (v - mu) * ri * gw[c] + gb[c];
    }
    __syncthreads();
    size_t ob = (size_t)bz * HW * CC;
#pragma unroll
    for (int r = 0; r < 4; r++) {
        int i = i0 + ty + r * 8;
        float v = tile[tx][ty + r * 8];
        bf16 h = __float2bfloat16(v);
        size_t idx = ob + (size_t)i * CC + c0 + tx;
        g_ht_hi[idx] = h;
        g_ht_lo[idx] = __float2bfloat16(v - __bfloat162float(h));
    }
}

// fp32 -> bf16 hi/lo split
__global__ void wconv(const float* __restrict__ w, bf16* __restrict__ hi,
                      bf16* __restrict__ lo, int n) {
    int i = blockIdx.x * blockDim.x + threadIdx.x;
    if (i < n) {
        float v = w[i];
        bf16 h = __float2bfloat16(v);
        hi[i] = h;
        lo[i] = __float2bfloat16(v - __bfloat162float(h));
    }
}

// Row softmax over 1024 columns; writes P as bf16 hi/lo
__global__ void softmax_kernel(const float* __restrict__ S,
                               bf16* __restrict__ Ph, bf16* __restrict__ Pl) {
    const float* row = S + (size_t)blockIdx.x * HW;
    int t = threadIdx.x;
    float4 v = ((const float4*)row)[t];

    __shared__ float sh[256];
    float m = fmaxf(fmaxf(v.x, v.y), fmaxf(v.z, v.w));
    sh[t] = m;
    __syncthreads();
    for (int o = 128; o > 0; o >>= 1) {
        if (t < o) sh[t] = fmaxf(sh[t], sh[t + o]);
        __syncthreads();
    }
    m = sh[0];
    __syncthreads();

    v.x = __expf(v.x - m); v.y = __expf(v.y - m);
    v.z = __expf(v.z - m); v.w = __expf(v.w - m);
    sh[t] = v.x + v.y + v.z + v.w;
    __syncthreads();
    for (int o = 128; o > 0; o >>= 1) {
        if (t < o) sh[t] += sh[t + o];
        __syncthreads();
    }
    float inv = 1.0f / sh[0];
    float p[4] = {v.x * inv, v.y * inv, v.z * inv, v.w * inv};
    size_t base = (size_t)blockIdx.x * HW + t * 4;
#pragma unroll
    for (int e = 0; e < 4; e++) {
        bf16 h = __float2bfloat16(p[e]);
        Ph[base + e] = h;
        Pl[base + e] = __float2bfloat16(p[e] - __bfloat162float(h));
    }
}

// ---------------------------------------------------------------------------
extern "C" void kernel_launch(void* const* d_in, const int* in_sizes, int n_in,
                              void* d_out, int out_size) {
    const float* x    = (const float*)d_in[0];
    const float* gn_w = (const float*)d_in[2];
    const float* gn_b = (const float*)d_in[3];
    const float* q_w  = (const float*)d_in[4];
    const float* q_b  = (const float*)d_in[5];
    const float* k_w  = (const float*)d_in[6];
    const float* k_b  = (const float*)d_in[7];
    const float* v_w  = (const float*)d_in[8];
    const float* v_b  = (const float*)d_in[9];
    const float* p_w  = (const float*)d_in[10];
    const float* p_b  = (const float*)d_in[11];
    float* out = (float*)d_out;

    bf16 *ht_hi, *ht_lo, *qt_hi, *qt_lo, *kt_hi, *kt_lo, *v_hi, *v_lo;
    bf16 *p_hi, *p_lo, *ot_hi, *ot_lo, *w_hi, *w_lo;
    float* s;
    cudaGetSymbolAddress((void**)&ht_hi, g_ht_hi);
    cudaGetSymbolAddress((void**)&ht_lo, g_ht_lo);
    cudaGetSymbolAddress((void**)&qt_hi, g_qt_hi);
    cudaGetSymbolAddress((void**)&qt_lo, g_qt_lo);
    cudaGetSymbolAddress((void**)&kt_hi, g_kt_hi);
    cudaGetSymbolAddress((void**)&kt_lo, g_kt_lo);
    cudaGetSymbolAddress((void**)&v_hi, g_v_hi);
    cudaGetSymbolAddress((void**)&v_lo, g_v_lo);
    cudaGetSymbolAddress((void**)&p_hi, g_p_hi);
    cudaGetSymbolAddress((void**)&p_lo, g_p_lo);
    cudaGetSymbolAddress((void**)&ot_hi, g_ot_hi);
    cudaGetSymbolAddress((void**)&ot_lo, g_ot_lo);
    cudaGetSymbolAddress((void**)&w_hi, g_w_hi);
    cudaGetSymbolAddress((void**)&w_lo, g_w_lo);
    cudaGetSymbolAddress((void**)&s, g_s);

    cudaFuncSetAttribute(gemm_mma<0>, cudaFuncAttributeMaxDynamicSharedMemorySize, SMEM_TOTAL);
    cudaFuncSetAttribute(gemm_mma<1>, cudaFuncAttributeMaxDynamicSharedMemorySize, SMEM_TOTAL);
    cudaFuncSetAttribute(gemm_mma<2>, cudaFuncAttributeMaxDynamicSharedMemorySize, SMEM_TOTAL);
    cudaFuncSetAttribute(gemm_mma<3>, cudaFuncAttributeMaxDynamicSharedMemorySize, SMEM_TOTAL);
    cudaFuncSetAttribute(gemm_mma<4>, cudaFuncAttributeMaxDynamicSharedMemorySize, SMEM_TOTAL);

    const size_t sHC = (size_t)HW * CC;
    const size_t sSS = (size_t)HW * HW;
    const int NW = CC * CC;
    const float scale = 0.044194173824159216f;  // 512^-0.5

    gn_stats<<<BATCH * G, 256>>>(x);
    gn_transpose<<<dim3(HW / 32, CC / 32, BATCH), dim3(32, 8)>>>(x, gn_w, gn_b);

    wconv<<<NW / 256, 256>>>(q_w, w_hi + 0 * NW, w_lo + 0 * NW, NW);
    wconv<<<NW / 256, 256>>>(k_w, w_hi + 1 * NW, w_lo + 1 * NW, NW);
    wconv<<<NW / 256, 256>>>(v_w, w_hi + 2 * NW, w_lo + 2 * NW, NW);
    wconv<<<NW / 256, 256>>>(p_w, w_hi + 3 * NW, w_lo + 3 * NW, NW);

    // Qt[i][c] = Ht[i]·Wq[c] + qb[c]   (bias on n)
    gemm_mma<0><<<dim3(4, 8, BATCH), 256, SMEM_TOTAL>>>(
        ht_hi, ht_lo, sHC, w_hi + 0 * NW, w_lo + 0 * NW, 0, CC,
        q_b, 0.f, nullptr, qt_hi, qt_lo, nullptr, CC, sHC);
    // Kt[i][c]
    gemm_mma<0><<<dim3(4, 8, BATCH), 256, SMEM_TOTAL>>>(
        ht_hi, ht_lo, sHC, w_hi + 1 * NW, w_lo + 1 * NW, 0, CC,
        k_b, 0.f, nullptr, kt_hi, kt_lo, nullptr, CC, sHC);
    // V[c][j] = Wv[c]·Ht[j] + vb[c]    (bias on m)
    gemm_mma<1><<<dim3(8, 4, BATCH), 256, SMEM_TOTAL>>>(
        w_hi + 2 * NW, w_lo + 2 * NW, 0, ht_hi, ht_lo, sHC, CC,
        v_b, 0.f, nullptr, v_hi, v_lo, nullptr, HW, sHC);
    // S[i][j] = scale * Qt[i]·Kt[j]
    gemm_mma<2><<<dim3(8, 8, BATCH), 256, SMEM_TOTAL>>>(
        qt_hi, qt_lo, sHC, kt_hi, kt_lo, sHC, CC,
        nullptr, scale, nullptr, nullptr, nullptr, s, HW, sSS);

    softmax_kernel<<<BATCH * HW, 256>>>(s, p_hi, p_lo);

    // Ot[i][c] = P[i]·V[c]   (K = 1024)
    gemm_mma<3><<<dim3(4, 8, BATCH), 256, SMEM_TOTAL>>>(
        p_hi, p_lo, sSS, v_hi, v_lo, sHC, HW,
        nullptr, 0.f, nullptr, ot_hi, ot_lo, nullptr, CC, sHC);
    // out[d][i] = x[d][i] + Wp[d]·Ot[i] + pb[d]
    gemm_mma<4><<<dim3(8, 4, BATCH), 256, SMEM_TOTAL>>>(
        w_hi + 3 * NW, w_lo + 3 * NW, 0, ot_hi, ot_lo, sHC, CC,
        p_b, 0.f, x, nullptr, nullptr, out, HW, sHC);
}

// round 5
// speedup vs baseline: 2.7289x; 1.2029x over previous
#include <cuda_runtime.h>
#include <cuda_bf16.h>
#include <cstdint>

#define BATCH 16
#define CC 512
#define HW 1024
#define G 32
#define CG 16
#define EPS 1e-5f

typedef __nv_bfloat16 bf16;

// ---------------------------------------------------------------------------
// Scratch (device globals)
// ---------------------------------------------------------------------------
__device__ float g_stats[BATCH * G * 2];
__device__ __align__(16) bf16 g_ht_hi[BATCH * HW * CC], g_ht_lo[BATCH * HW * CC];
__device__ __align__(16) bf16 g_qt_hi[BATCH * HW * CC], g_qt_lo[BATCH * HW * CC];
__device__ __align__(16) bf16 g_kt_hi[BATCH * HW * CC], g_kt_lo[BATCH * HW * CC];
__device__ __align__(16) bf16 g_v_hi[BATCH * CC * HW],  g_v_lo[BATCH * CC * HW];
__device__ __align__(16) float g_s[(size_t)BATCH * HW * HW];
__device__ __align__(16) bf16 g_p_hi[(size_t)BATCH * HW * HW];
__device__ __align__(16) bf16 g_p_lo[(size_t)BATCH * HW * HW];
__device__ __align__(16) bf16 g_ot_hi[BATCH * HW * CC], g_ot_lo[BATCH * HW * CC];
__device__ __align__(16) bf16 g_w_hi[4 * CC * CC], g_w_lo[4 * CC * CC];

// ---------------------------------------------------------------------------
// PTX helpers (sm_80-class features only: cp.async + mma.sync + ldmatrix)
// ---------------------------------------------------------------------------
__device__ __forceinline__ uint32_t smem_u32(const void* p) {
    uint32_t a;
    asm("{ .reg .u64 t; cvta.to.shared.u64 t, %1; cvt.u32.u64 %0, t; }"
        : "=r"(a) : "l"(p));
    return a;
}
__device__ __forceinline__ void cpa16(uint32_t dst, const void* src) {
    asm volatile("cp.async.ca.shared.global [%0], [%1], 16;"
                 :: "r"(dst), "l"(src));
}
#define CP_COMMIT() asm volatile("cp.async.commit_group;" ::: "memory")
#define CP_WAIT1() asm volatile("cp.async.wait_group 1;" ::: "memory")
#define CP_WAIT0() asm volatile("cp.async.wait_group 0;" ::: "memory")

__device__ __forceinline__ void ldsm_x4(uint32_t* r, uint32_t addr) {
    asm volatile(
        "ldmatrix.sync.aligned.m8n8.x4.shared.b16 {%0,%1,%2,%3}, [%4];"
        : "=r"(r[0]), "=r"(r[1]), "=r"(r[2]), "=r"(r[3]) : "r"(addr));
}
__device__ __forceinline__ void mma16816(float* c, const uint32_t* a,
                                         const uint32_t* b) {
    asm volatile(
        "mma.sync.aligned.m16n8k16.row.col.f32.bf16.bf16.f32 "
        "{%0,%1,%2,%3}, {%4,%5,%6,%7}, {%8,%9}, {%0,%1,%2,%3};"
        : "+f"(c[0]), "+f"(c[1]), "+f"(c[2]), "+f"(c[3])
        : "r"(a[0]), "r"(a[1]), "r"(a[2]), "r"(a[3]), "r"(b[0]), "r"(b[1]));
}

// ---------------------------------------------------------------------------
// Split-bf16 MMA GEMM: D[m][n] = sum_k A[m][k]*B[n][k]  (both K-contiguous)
// 128x128 block tile, BK=32, 256 thr (8 warps, 32x64 warp tiles),
// cp.async double-buffered, ldmatrix fragment loads.
// MODE 0: +bias[n], bf16 hi/lo out     (Q/K proj)
// MODE 1: +bias[m], bf16 hi/lo out     (V proj)
// MODE 2: *scale,   f32 out            (scores)
// MODE 3: plain,    bf16 hi/lo out     (attn @ V)
// MODE 4: +bias[m]+resid, f32 out      (final proj)
// ---------------------------------------------------------------------------
#define PADB 80u             // bytes per smem row (64 data + 16 pad)
#define MATB 10240u          // 128 rows * 80 B
#define STAGEB 40960u        // 4 matrices (Ah, Al, Bh, Bl)
#define SMEM_TOTAL (2 * STAGEB)

template <int MODE>
__global__ void __launch_bounds__(256, 2)
gemm_mma(const bf16* __restrict__ Ahi, const bf16* __restrict__ Alo, size_t sA,
         const bf16* __restrict__ Bhi, const bf16* __restrict__ Blo, size_t sB,
         int K, const float* __restrict__ bias, float scale,
         const float* __restrict__ resid,
         bf16* __restrict__ Ohi, bf16* __restrict__ Olo, float* __restrict__ Of,
         int ldO, size_t sO) {
    extern __shared__ char smem[];
    const uint32_t sb = smem_u32(smem);

    const int t = threadIdx.x;
    const int w = t >> 5, lane = t & 31;
    const int g = lane >> 2, tg = lane & 3;
    const int wm = (w >> 1) * 32, wn = (w & 1) * 64;
    const int bz = blockIdx.z;
    const int n0 = blockIdx.x * 128, m0 = blockIdx.y * 128;

    const bf16* arh = Ahi + bz * sA + (size_t)m0 * K;
    const bf16* arl = Alo + bz * sA + (size_t)m0 * K;
    const bf16* brh = Bhi + bz * sB + (size_t)n0 * K;
    const bf16* brl = Blo + bz * sB + (size_t)n0 * K;

    float acc[2][8][4];
#pragma unroll
    for (int i = 0; i < 2; i++)
#pragma unroll
        for (int j = 0; j < 8; j++)
#pragma unroll
            for (int e = 0; e < 4; e++) acc[i][j][e] = 0.f;

    // cp.async loader mapping: ids t and t+256 cover 512 16B segments
    const int row_l = t >> 2, c16 = t & 3;
    const uint32_t soff0 = (uint32_t)row_l * PADB + c16 * 16;
    const int row_l2 = (t + 256) >> 2;
    const uint32_t soff1 = (uint32_t)row_l2 * PADB + c16 * 16;

    // ldmatrix per-lane source addresses (within a stage matrix)
    const uint32_t a_row = (uint32_t)(wm + ((lane >> 3) & 1) * 8 + (lane & 7));
    const uint32_t a_kb = ((lane >> 4) & 1) * 16;
    const uint32_t b_row = (uint32_t)(wn + ((lane >> 4) & 1) * 8 + (lane & 7));
    const uint32_t b_kb = ((lane >> 3) & 1) * 16;

    const int nsteps = K >> 5;

    {   // prologue: stage 0
        size_t g0 = (size_t)row_l * K + c16 * 8;
        size_t g1 = (size_t)row_l2 * K + c16 * 8;
        uint32_t b0 = sb;
        cpa16(b0 + soff0, arh + g0);            cpa16(b0 + soff1, arh + g1);
        cpa16(b0 + MATB + soff0, arl + g0);     cpa16(b0 + MATB + soff1, arl + g1);
        cpa16(b0 + 2 * MATB + soff0, brh + g0); cpa16(b0 + 2 * MATB + soff1, brh + g1);
        cpa16(b0 + 3 * MATB + soff0, brl + g0); cpa16(b0 + 3 * MATB + soff1, brl + g1);
        CP_COMMIT();
    }

    for (int s = 0; s < nsteps; s++) {
        if (s + 1 < nsteps) {
            int k0 = (s + 1) << 5;
            uint32_t b0 = sb + ((s + 1) & 1) * STAGEB;
            size_t g0 = (size_t)row_l * K + k0 + c16 * 8;
            size_t g1 = (size_t)row_l2 * K + k0 + c16 * 8;
            cpa16(b0 + soff0, arh + g0);            cpa16(b0 + soff1, arh + g1);
            cpa16(b0 + MATB + soff0, arl + g0);     cpa16(b0 + MATB + soff1, arl + g1);
            cpa16(b0 + 2 * MATB + soff0, brh + g0); cpa16(b0 + 2 * MATB + soff1, brh + g1);
            cpa16(b0 + 3 * MATB + soff0, brl + g0); cpa16(b0 + 3 * MATB + soff1, brl + g1);
            CP_COMMIT();
            CP_WAIT1();
        } else {
            CP_WAIT0();
        }
        __syncthreads();

        uint32_t stg = sb + (s & 1) * STAGEB;
        uint32_t pAh = stg, pAl = stg + MATB;
        uint32_t pBh = stg + 2 * MATB, pBl = stg + 3 * MATB;
#pragma unroll
        for (int kk = 0; kk < 2; kk++) {
            uint32_t kb = (uint32_t)kk * 32;
            uint32_t Ah[2][4], Al[2][4];
#pragma unroll
            for (int mf = 0; mf < 2; mf++) {
                uint32_t ad = (a_row + mf * 16) * PADB + kb + a_kb;
                ldsm_x4(Ah[mf], pAh + ad);
                ldsm_x4(Al[mf], pAl + ad);
            }
#pragma unroll
            for (int p = 0; p < 4; p++) {
                uint32_t bd = (b_row + p * 16) * PADB + kb + b_kb;
                uint32_t Bh[4], Bl[4];
                ldsm_x4(Bh, pBh + bd);
                ldsm_x4(Bl, pBl + bd);
#pragma unroll
                for (int mf = 0; mf < 2; mf++) {
                    mma16816(acc[mf][2 * p], Ah[mf], Bh);
                    mma16816(acc[mf][2 * p], Ah[mf], Bl);
                    mma16816(acc[mf][2 * p], Al[mf], Bh);
                    mma16816(acc[mf][2 * p + 1], Ah[mf], Bh + 2);
                    mma16816(acc[mf][2 * p + 1], Ah[mf], Bl + 2);
                    mma16816(acc[mf][2 * p + 1], Al[mf], Bh + 2);
                }
            }
        }
        __syncthreads();
    }

    // ---- epilogue: direct row-major [m][n] store -------------------------
#pragma unroll
    for (int mf = 0; mf < 2; mf++) {
        int mA = m0 + wm + mf * 16 + g;
        int mB = mA + 8;
        float bmA = 0.f, bmB = 0.f;
        if (MODE == 1 || MODE == 4) { bmA = bias[mA]; bmB = bias[mB]; }
#pragma unroll
        for (int nf = 0; nf < 8; nf++) {
            int n = n0 + wn + nf * 8 + tg * 2;
            float v0 = acc[mf][nf][0], v1 = acc[mf][nf][1];
            float v2 = acc[mf][nf][2], v3 = acc[mf][nf][3];
            if (MODE == 0) {
                float bn0 = bias[n], bn1 = bias[n + 1];
                v0 += bn0; v1 += bn1; v2 += bn0; v3 += bn1;
            }
            if (MODE == 1 || MODE == 4) { v0 += bmA; v1 += bmA; v2 += bmB; v3 += bmB; }
            if (MODE == 2) { v0 *= scale; v1 *= scale; v2 *= scale; v3 *= scale; }
            size_t iA = bz * sO + (size_t)mA * ldO + n;
            size_t iB = bz * sO + (size_t)mB * ldO + n;
            if (MODE == 4) {
                v0 += resid[iA]; v1 += resid[iA + 1];
                v2 += resid[iB]; v3 += resid[iB + 1];
            }
            if (MODE == 2 || MODE == 4) {
                *(float2*)&Of[iA] = make_float2(v0, v1);
                *(float2*)&Of[iB] = make_float2(v2, v3);
            } else {
                bf16 h0 = __float2bfloat16(v0), h1 = __float2bfloat16(v1);
                bf16 h2 = __float2bfloat16(v2), h3 = __float2bfloat16(v3);
                __nv_bfloat162 hA; hA.x = h0; hA.y = h1;
                __nv_bfloat162 hB; hB.x = h2; hB.y = h3;
                *(__nv_bfloat162*)&Ohi[iA] = hA;
                *(__nv_bfloat162*)&Ohi[iB] = hB;
                __nv_bfloat162 lA, lB;
                lA.x = __float2bfloat16(v0 - __bfloat162float(h0));
                lA.y = __float2bfloat16(v1 - __bfloat162float(h1));
                lB.x = __float2bfloat16(v2 - __bfloat162float(h2));
                lB.y = __float2bfloat16(v3 - __bfloat162float(h3));
                *(__nv_bfloat162*)&Olo[iA] = lA;
                *(__nv_bfloat162*)&Olo[iB] = lB;
            }
        }
    }
}

// ---------------------------------------------------------------------------
// GroupNorm stats
// ---------------------------------------------------------------------------
__global__ void gn_stats(const float* __restrict__ x) {
    int bg = blockIdx.x;
    int bb = bg / G, g = bg % G;
    const float* xp = x + ((size_t)bb * CC + (size_t)g * CG) * HW;
    const int n = CG * HW;

    float s = 0.f, ss = 0.f;
    for (int i = threadIdx.x; i < n; i += blockDim.x) {
        float v = xp[i];
        s += v;
        ss += v * v;
    }
    __shared__ float sh0[256], sh1[256];
    sh0[threadIdx.x] = s;
    sh1[threadIdx.x] = ss;
    __syncthreads();
    for (int o = 128; o > 0; o >>= 1) {
        if (threadIdx.x < o) {
            sh0[threadIdx.x] += sh0[threadIdx.x + o];
            sh1[threadIdx.x] += sh1[threadIdx.x + o];
        }
        __syncthreads();
    }
    if (threadIdx.x == 0) {
        float mu = sh0[0] / n;
        float var = sh1[0] / n - mu * mu;
        g_stats[bg * 2] = mu;
        g_stats[bg * 2 + 1] = rsqrtf(var + EPS);
    }
}

// GroupNorm apply + transpose: x[b][c][i] -> Ht[b][i][c] bf16 hi/lo
__global__ void gn_transpose(const float* __restrict__ x,
                             const float* __restrict__ gw,
                             const float* __restrict__ gb) {
    __shared__ float tile[32][33];
    int bz = blockIdx.z;
    int i0 = blockIdx.x * 32, c0 = blockIdx.y * 32;
    int tx = threadIdx.x, ty = threadIdx.y;
    const float* xb = x + (size_t)bz * CC * HW;
#pragma unroll
    for (int r = 0; r < 4; r++) {
        int c = c0 + ty + r * 8;
        float mu = g_stats[(bz * G + (c >> 4)) * 2];
        float ri = g_stats[(bz * G + (c >> 4)) * 2 + 1];
        float v = xb[(size_t)c * HW + i0 + tx];
        tile[ty + r * 8][tx] = (v - mu) * ri * gw[c] + gb[c];
    }
    __syncthreads();
    size_t ob = (size_t)bz * HW * CC;
#pragma unroll
    for (int r = 0; r < 4; r++) {
        int i = i0 + ty + r * 8;
        float v = tile[tx][ty + r * 8];
        bf16 h = __float2bfloat16(v);
        size_t idx = ob + (size_t)i * CC + c0 + tx;
        g_ht_hi[idx] = h;
        g_ht_lo[idx] = __float2bfloat16(v - __bfloat162float(h));
    }
}

// fp32 -> bf16 hi/lo split for all 4 weight matrices in one launch
__global__ void wconv4(const float* __restrict__ w0, const float* __restrict__ w1,
                       const float* __restrict__ w2, const float* __restrict__ w3,
                       bf16* __restrict__ hi, bf16* __restrict__ lo) {
    const int NW = CC * CC;
    int i = blockIdx.x * blockDim.x + threadIdx.x;
    int which = blockIdx.y;
    const float* w = which == 0 ? w0 : which == 1 ? w1 : which == 2 ? w2 : w3;
    float v = w[i];
    bf16 h = __float2bfloat16(v);
    hi[which * NW + i] = h;
    lo[which * NW + i] = __float2bfloat16(v - __bfloat162float(h));
}

// Row softmax over 1024 columns; writes P as bf16 hi/lo
__global__ void softmax_kernel(const float* __restrict__ S,
                               bf16* __restrict__ Ph, bf16* __restrict__ Pl) {
    const float* row = S + (size_t)blockIdx.x * HW;
    int t = threadIdx.x;
    float4 v = ((const float4*)row)[t];

    __shared__ float sh[256];
    float m = fmaxf(fmaxf(v.x, v.y), fmaxf(v.z, v.w));
    sh[t] = m;
    __syncthreads();
    for (int o = 128; o > 0; o >>= 1) {
        if (t < o) sh[t] = fmaxf(sh[t], sh[t + o]);
        __syncthreads();
    }
    m = sh[0];
    __syncthreads();

    v.x = __expf(v.x - m); v.y = __expf(v.y - m);
    v.z = __expf(v.z - m); v.w = __expf(v.w - m);
    sh[t] = v.x + v.y + v.z + v.w;
    __syncthreads();
    for (int o = 128; o > 0; o >>= 1) {
        if (t < o) sh[t] += sh[t + o];
        __syncthreads();
    }
    float inv = 1.0f / sh[0];
    float p[4] = {v.x * inv, v.y * inv, v.z * inv, v.w * inv};
    size_t base = (size_t)blockIdx.x * HW + t * 4;
#pragma unroll
    for (int e = 0; e < 4; e++) {
        bf16 h = __float2bfloat16(p[e]);
        Ph[base + e] = h;
        Pl[base + e] = __float2bfloat16(p[e] - __bfloat162float(h));
    }
}

// ---------------------------------------------------------------------------
extern "C" void kernel_launch(void* const* d_in, const int* in_sizes, int n_in,
                              void* d_out, int out_size) {
    const float* x    = (const float*)d_in[0];
    const float* gn_w = (const float*)d_in[2];
    const float* gn_b = (const float*)d_in[3];
    const float* q_w  = (const float*)d_in[4];
    const float* q_b  = (const float*)d_in[5];
    const float* k_w  = (const float*)d_in[6];
    const float* k_b  = (const float*)d_in[7];
    const float* v_w  = (const float*)d_in[8];
    const float* v_b  = (const float*)d_in[9];
    const float* p_w  = (const float*)d_in[10];
    const float* p_b  = (const float*)d_in[11];
    float* out = (float*)d_out;

    bf16 *ht_hi, *ht_lo, *qt_hi, *qt_lo, *kt_hi, *kt_lo, *v_hi, *v_lo;
    bf16 *p_hi, *p_lo, *ot_hi, *ot_lo, *w_hi, *w_lo;
    float* s;
    cudaGetSymbolAddress((void**)&ht_hi, g_ht_hi);
    cudaGetSymbolAddress((void**)&ht_lo, g_ht_lo);
    cudaGetSymbolAddress((void**)&qt_hi, g_qt_hi);
    cudaGetSymbolAddress((void**)&qt_lo, g_qt_lo);
    cudaGetSymbolAddress((void**)&kt_hi, g_kt_hi);
    cudaGetSymbolAddress((void**)&kt_lo, g_kt_lo);
    cudaGetSymbolAddress((void**)&v_hi, g_v_hi);
    cudaGetSymbolAddress((void**)&v_lo, g_v_lo);
    cudaGetSymbolAddress((void**)&p_hi, g_p_hi);
    cudaGetSymbolAddress((void**)&p_lo, g_p_lo);
    cudaGetSymbolAddress((void**)&ot_hi, g_ot_hi);
    cudaGetSymbolAddress((void**)&ot_lo, g_ot_lo);
    cudaGetSymbolAddress((void**)&w_hi, g_w_hi);
    cudaGetSymbolAddress((void**)&w_lo, g_w_lo);
    cudaGetSymbolAddress((void**)&s, g_s);

    cudaFuncSetAttribute(gemm_mma<0>, cudaFuncAttributeMaxDynamicSharedMemorySize, SMEM_TOTAL);
    cudaFuncSetAttribute(gemm_mma<1>, cudaFuncAttributeMaxDynamicSharedMemorySize, SMEM_TOTAL);
    cudaFuncSetAttribute(gemm_mma<2>, cudaFuncAttributeMaxDynamicSharedMemorySize, SMEM_TOTAL);
    cudaFuncSetAttribute(gemm_mma<3>, cudaFuncAttributeMaxDynamicSharedMemorySize, SMEM_TOTAL);
    cudaFuncSetAttribute(gemm_mma<4>, cudaFuncAttributeMaxDynamicSharedMemorySize, SMEM_TOTAL);

    const size_t sHC = (size_t)HW * CC;
    const size_t sSS = (size_t)HW * HW;
    const int NW = CC * CC;
    const float scale = 0.044194173824159216f;  // 512^-0.5

    gn_stats<<<BATCH * G, 256>>>(x);
    gn_transpose<<<dim3(HW / 32, CC / 32, BATCH), dim3(32, 8)>>>(x, gn_w, gn_b);
    wconv4<<<dim3(NW / 256, 4), 256>>>(q_w, k_w, v_w, p_w, w_hi, w_lo);

    // Qt[i][c] = Ht[i]·Wq[c] + qb[c]   (bias on n)
    gemm_mma<0><<<dim3(4, 8, BATCH), 256, SMEM_TOTAL>>>(
        ht_hi, ht_lo, sHC, w_hi + 0 * NW, w_lo + 0 * NW, 0, CC,
        q_b, 0.f, nullptr, qt_hi, qt_lo, nullptr, CC, sHC);
    // Kt[i][c]
    gemm_mma<0><<<dim3(4, 8, BATCH), 256, SMEM_TOTAL>>>(
        ht_hi, ht_lo, sHC, w_hi + 1 * NW, w_lo + 1 * NW, 0, CC,
        k_b, 0.f, nullptr, kt_hi, kt_lo, nullptr, CC, sHC);
    // V[c][j] = Wv[c]·Ht[j] + vb[c]    (bias on m)
    gemm_mma<1><<<dim3(8, 4, BATCH), 256, SMEM_TOTAL>>>(
        w_hi + 2 * NW, w_lo + 2 * NW, 0, ht_hi, ht_lo, sHC, CC,
        v_b, 0.f, nullptr, v_hi, v_lo, nullptr, HW, sHC);
    // S[i][j] = scale * Qt[i]·Kt[j]
    gemm_mma<2><<<dim3(8, 8, BATCH), 256, SMEM_TOTAL>>>(
        qt_hi, qt_lo, sHC, kt_hi, kt_lo, sHC, CC,
        nullptr, scale, nullptr, nullptr, nullptr, s, HW, sSS);

    softmax_kernel<<<BATCH * HW, 256>>>(s, p_hi, p_lo);

    // Ot[i][c] = P[i]·V[c]   (K = 1024)
    gemm_mma<3><<<dim3(4, 8, BATCH), 256, SMEM_TOTAL>>>(
        p_hi, p_lo, sSS, v_hi, v_lo, sHC, HW,
        nullptr, 0.f, nullptr, ot_hi, ot_lo, nullptr, CC, sHC);
    // out[d][i] = x[d][i] + Wp[d]·Ot[i] + pb[d]
    gemm_mma<4><<<dim3(8, 4, BATCH), 256, SMEM_TOTAL>>>(
        w_hi + 3 * NW, w_lo + 3 * NW, 0, ot_hi, ot_lo, sHC, CC,
        p_b, 0.f, x, nullptr, nullptr, out, HW, sHC);
}